// round 17
// baseline (speedup 1.0000x reference)
#include <cuda_runtime.h>
#include <cuda_bf16.h>
#include <cstdint>

// ---------------------------------------------------------------------------
// BiLSTM_55499567398998 — split architecture, pure CUDA-core fp32:
//   K2: time-parallel GEMM  xg = out1 @ Wih2f^T + b2   (f32x2 FMA, full chip)
//   K3: recurrent scan (k=152, h-part only) + fused backward-step + heads
// (tcgen05 is unusable here: harness lowers through compute_103 PTX, which
//  rejects tcgen05.* — arch-variant 103a features don't exist at that target)
// ---------------------------------------------------------------------------

#define B_    1024
#define T_    128
#define H1_   50
#define G1_   200
#define H2_   150
#define G2_   600
#define GP_   608      // padded gates
#define R1_   8
#define R2_   8
#define KH_   152      // scan k: h(150) + pad(2)
#define WS2_  156      // smem weight row stride (bank-conflict-free, 16B-mult)
#define NCW2_ 320      // gate rows cached in smem
#define NKQH_ 38       // 152/4
#define NKQI_ 25       // 100/4 (GEMM k-quads)
#define MROWS (B_ * T_)   // 131072

// scratch (device globals)
__device__ float g_out1[B_ * T_ * 100];
__device__ float g_Whr [GP_ * KH_];            // Whh2f rows [608][152]
__device__ float g_WQh [NKQH_ * GP_ * 4];      // scan-weight quad-major stream
__device__ float g_WQi [NKQI_ * GP_ * 4];      // GEMM-weight quad-major stream
__device__ float g_xg  [(size_t)MROWS * GP_];  // xg + bias, f32

__device__ __forceinline__ float sigf(float z) { return 1.0f / (1.0f + __expf(-z)); }
__device__ __forceinline__ float tanhfast(float x) {
    float t = __expf(-2.0f * fabsf(x));
    return copysignf((1.0f - t) / (1.0f + t), x);
}
__device__ __forceinline__ float lrelu(float z) { return z > 0.0f ? z : 0.3f * z; }

__device__ __forceinline__ unsigned long long pack2(float lo, float hi) {
    unsigned long long r;
    asm("mov.b64 %0, {%1, %2};" : "=l"(r) : "f"(lo), "f"(hi));
    return r;
}
__device__ __forceinline__ void fmaf2(unsigned long long& acc,
                                      unsigned long long a, unsigned long long b) {
    asm("fma.rn.f32x2 %0, %1, %2, %0;" : "+l"(acc) : "l"(a), "l"(b));
}
__device__ __forceinline__ float hsum2(unsigned long long v) {
    float lo, hi;
    asm("mov.b64 {%0, %1}, %2;" : "=f"(lo), "=f"(hi) : "l"(v));
    return lo + hi;
}

// ---------------------------------------------------------------------------
// K0: prep — scan weights (row-major + quad-major) and GEMM weights (quad)
// ---------------------------------------------------------------------------
__global__ void prep_kernel(const float* __restrict__ Whh2f,
                            const float* __restrict__ Wih2f)
{
    int j = blockIdx.x;          // 608
    int tid = threadIdx.x;       // 128

    for (int k = tid; k < KH_; k += 128) {
        float v = (j < G2_ && k < H2_) ? Whh2f[j * H2_ + k] : 0.0f;
        g_Whr[j * KH_ + k] = v;
        g_WQh[(k >> 2) * (GP_ * 4) + j * 4 + (k & 3)] = v;
    }
    if (tid < 100) {
        int k = tid;
        float w = (j < G2_) ? Wih2f[j * 100 + k] : 0.0f;
        g_WQi[(k >> 2) * (GP_ * 4) + j * 4 + (k & 3)] = w;
    }
}

// ---------------------------------------------------------------------------
// K1: layer-1 scan (unchanged from measured-good version)
// ---------------------------------------------------------------------------
__global__ void __launch_bounds__(256)
lstm1_kernel(const float* __restrict__ x,
             const float* __restrict__ Wih_f, const float* __restrict__ Whh_f,
             const float* __restrict__ b_f,
             const float* __restrict__ Wih_b, const float* __restrict__ Whh_b,
             const float* __restrict__ b_b)
{
    const int dir = blockIdx.y;
    const float* Wih = dir ? Wih_b : Wih_f;
    const float* Whh = dir ? Whh_b : Whh_f;
    const float* bv  = dir ? b_b  : b_f;
    const int row0 = blockIdx.x * R1_;
    const int tid  = threadIdx.x;

    __shared__ float h_s[R1_][H1_];
    __shared__ float g_s[R1_][G1_];
    __shared__ float x_s[R1_][T_];

    for (int i = tid; i < R1_ * T_; i += 256)
        x_s[i / T_][i % T_] = x[(row0 + i / T_) * T_ + (i % T_)];
    for (int i = tid; i < R1_ * H1_; i += 256)
        h_s[i / H1_][i % H1_] = 0.0f;

    unsigned long long wp[H1_ / 2];
    float wih_j = 0.0f, bj = 0.0f;
    if (tid < G1_) {
#pragma unroll
        for (int kk = 0; kk < H1_ / 2; kk++) {
            float2 wv = *(const float2*)&Whh[tid * H1_ + 2 * kk];
            wp[kk] = pack2(wv.x, wv.y);
        }
        wih_j = Wih[tid];
        bj    = bv[tid];
    }

    const int u0 = tid, u1 = tid + 256;
    const int r0 = u0 / H1_, k0 = u0 % H1_;
    const int r1 = u1 / H1_, k1 = u1 % H1_;
    float c0 = 0.0f, c1 = 0.0f;

    __syncthreads();

    for (int t = 0; t < T_; t++) {
        const int tt = dir ? (T_ - 1 - t) : t;

        if (tid < G1_) {
            unsigned long long acc[R1_];
#pragma unroll
            for (int r = 0; r < R1_; r++)
                acc[r] = pack2(fmaf(x_s[r][tt], wih_j, bj), 0.0f);
#pragma unroll
            for (int kk = 0; kk < H1_ / 2; kk++) {
#pragma unroll
                for (int r = 0; r < R1_; r++) {
                    unsigned long long hv = *(const unsigned long long*)&h_s[r][2 * kk];
                    fmaf2(acc[r], wp[kk], hv);
                }
            }
#pragma unroll
            for (int r = 0; r < R1_; r++) g_s[r][tid] = hsum2(acc[r]);
        }
        __syncthreads();

        {
            float i_ = g_s[r0][k0], f_ = g_s[r0][H1_ + k0];
            float gg = g_s[r0][2 * H1_ + k0], o_ = g_s[r0][3 * H1_ + k0];
            c0 = sigf(f_) * c0 + sigf(i_) * tanhfast(gg);
            float h = sigf(o_) * tanhfast(c0);
            h_s[r0][k0] = h;
            g_out1[(row0 + r0) * (T_ * 100) + tt * 100 + dir * H1_ + k0] = h;
        }
        if (u1 < 400) {
            float i_ = g_s[r1][k1], f_ = g_s[r1][H1_ + k1];
            float gg = g_s[r1][2 * H1_ + k1], o_ = g_s[r1][3 * H1_ + k1];
            c1 = sigf(f_) * c1 + sigf(i_) * tanhfast(gg);
            float h = sigf(o_) * tanhfast(c1);
            h_s[r1][k1] = h;
            g_out1[(row0 + r1) * (T_ * 100) + tt * 100 + dir * H1_ + k1] = h;
        }
        __syncthreads();
    }
}

// ---------------------------------------------------------------------------
// K2: xg GEMM, pure f32x2.  xg[m][j] = sum_k out1[m][k]*Wih2f[j][k] + b2[j]
//   1024 CTAs x 608 threads.  m-tile = 128 rows (contiguous 51.2KB A copy).
//   Thread j owns gate j for all 128 rows (16 chunks of 8).
//   Weights: coalesced LDG from quad-major g_WQi (L2-resident, 243KB).
//   v: broadcast LDS.128.  Stores: warp = 32 consecutive j -> 128B lines.
// ---------------------------------------------------------------------------
#define SMEMG_BYTES (128 * 100 * 4)    // 51,200 B

__global__ void __launch_bounds__(608, 1)
xg_gemm_kernel(const float* __restrict__ b2)
{
    extern __shared__ float a_s[];                 // [128][100]
    const int tid = threadIdx.x;
    const int j   = tid;
    const int m0  = blockIdx.x * 128;

    // A tile is contiguous in gmem: straight coalesced float4 copy
    {
        const float4* src = (const float4*)(g_out1 + (size_t)m0 * 100);
        float4* dst = (float4*)a_s;
        for (int i = tid; i < 128 * 100 / 4; i += 608) dst[i] = src[i];
    }
    __syncthreads();

    const float bj = (j < G2_) ? b2[j] : 0.0f;
    const float4* wqi = (const float4*)g_WQi + j;  // stride GP_ per kq

#pragma unroll 4
    for (int rc = 0; rc < 16; rc++) {
        unsigned long long acc[8];
#pragma unroll
        for (int r = 0; r < 8; r++) acc[r] = pack2(bj, 0.0f);

#pragma unroll 5
        for (int kq = 0; kq < NKQI_; kq++) {
            float4 wf = wqi[kq * GP_];             // coalesced, L2-hot
            ulonglong2 w = *(const ulonglong2*)&wf;
            const float* vb = a_s + (rc * 8) * 100 + kq * 4;
#pragma unroll
            for (int r = 0; r < 8; r++) {
                ulonglong2 v = *(const ulonglong2*)(vb + r * 100);
                fmaf2(acc[r], w.x, v.x);
                fmaf2(acc[r], w.y, v.y);
            }
        }
#pragma unroll
        for (int r = 0; r < 8; r++)
            g_xg[(size_t)(m0 + rc * 8 + r) * GP_ + j] = hsum2(acc[r]);
    }
}

// ---------------------------------------------------------------------------
// K3: layer-2 recurrent scan (k=152) + fused backward-step + heads.
// ---------------------------------------------------------------------------
#define SMEM3_BYTES ((NCW2_ * WS2_ + R2_ * KH_ + R2_ * GP_) * 4)   // 224,000 B

__global__ void __launch_bounds__(608, 1)
lstm2_kernel(const float* __restrict__ Wih2b, const float* __restrict__ b2b,
             const float* __restrict__ rrs,
             const float* __restrict__ headW, const float* __restrict__ headb,
             const float* __restrict__ p1W,  const float* __restrict__ p1b,
             const float* __restrict__ p2W,  const float* __restrict__ p2b,
             const float* __restrict__ fcW,  const float* __restrict__ fcb,
             float* __restrict__ out)
{
    extern __shared__ float sm[];
    float* w_c = sm;                                          // NCW2_*WS2_
    float (*v_s)[KH_] = (float(*)[KH_])(sm + NCW2_ * WS2_);   // 8 x 152
    float (*g_s)[GP_] = (float(*)[GP_])(sm + NCW2_ * WS2_ + R2_ * KH_);

    const int tid  = threadIdx.x;
    const int row0 = blockIdx.x * R2_;
    const int j    = tid;

    for (int i = tid; i < NCW2_ * KH_; i += 608)
        w_c[(i / KH_) * WS2_ + (i % KH_)] = g_Whr[i];
    for (int i = tid; i < R2_ * KH_; i += 608)
        ((float*)v_s)[i] = 0.0f;                              // h=0, pads=0

    const int u0 = tid, u1 = tid + 608;
    const int r0 = u0 / H2_, k0 = u0 % H2_;
    const int r1 = u1 / H2_, k1 = u1 % H2_;
    float c0 = 0.0f, c1 = 0.0f;

    const float* xbase = g_xg + (size_t)row0 * T_ * GP_ + j;
    float xgv[R2_];
#pragma unroll
    for (int r = 0; r < R2_; r++) xgv[r] = __ldg(xbase + r * (T_ * GP_));

    __syncthreads();

    const float4* wqh = (const float4*)g_WQh + j;
    const ulonglong2* wsm = (const ulonglong2*)(w_c + j * WS2_);

    for (int t = 0; t < T_; t++) {
        unsigned long long acc[R2_];
#pragma unroll
        for (int r = 0; r < R2_; r++) acc[r] = pack2(xgv[r], 0.0f);

        if (t < T_ - 1) {  // prefetch next step's xg during the gate loop
#pragma unroll
            for (int r = 0; r < R2_; r++)
                xgv[r] = __ldg(xbase + r * (T_ * GP_) + (t + 1) * GP_);
        }

        if (j < NCW2_) {
#pragma unroll 2
            for (int kq = 0; kq < NKQH_; kq++) {
                ulonglong2 w = wsm[kq];
#pragma unroll
                for (int r = 0; r < R2_; r++) {
                    ulonglong2 v = *(const ulonglong2*)&v_s[r][kq * 4];
                    fmaf2(acc[r], w.x, v.x);
                    fmaf2(acc[r], w.y, v.y);
                }
            }
        } else {
#pragma unroll 2
            for (int kq = 0; kq < NKQH_; kq++) {
                float4 wf = wqh[kq * GP_];
                ulonglong2 w = *(const ulonglong2*)&wf;
#pragma unroll
                for (int r = 0; r < R2_; r++) {
                    ulonglong2 v = *(const ulonglong2*)&v_s[r][kq * 4];
                    fmaf2(acc[r], w.x, v.x);
                    fmaf2(acc[r], w.y, v.y);
                }
            }
        }
#pragma unroll
        for (int r = 0; r < R2_; r++) g_s[r][j] = hsum2(acc[r]);
        __syncthreads();

        {
            float i_ = g_s[r0][k0],            f_ = g_s[r0][H2_ + k0];
            float gg = g_s[r0][2 * H2_ + k0],  o_ = g_s[r0][3 * H2_ + k0];
            c0 = sigf(f_) * c0 + sigf(i_) * tanhfast(gg);
            v_s[r0][k0] = sigf(o_) * tanhfast(c0);
        }
        if (u1 < R2_ * H2_) {
            float i_ = g_s[r1][k1],            f_ = g_s[r1][H2_ + k1];
            float gg = g_s[r1][2 * H2_ + k1],  o_ = g_s[r1][3 * H2_ + k1];
            c1 = sigf(f_) * c1 + sigf(i_) * tanhfast(gg);
            v_s[r1][k1] = sigf(o_) * tanhfast(c1);
        }
        __syncthreads();
    }

    // ------------------------------------------------------------------
    // FUSED EPILOGUE. v_s[r][0:150] = h2f(127). Load out1[:,127] into xl_s.
    // ------------------------------------------------------------------
    float* xl_s = w_c;                               // 800 floats
    float (*net_s)[304] = (float(*)[304])(w_c + 1024);
    for (int i = tid; i < R2_ * 100; i += 608)
        xl_s[i] = g_out1[(row0 + i / 100) * (T_ * 100) + 127 * 100 + i % 100];
    __syncthreads();

    if (j < G2_) {                                   // backward gates
        float acc[R2_];
#pragma unroll
        for (int r = 0; r < R2_; r++) acc[r] = b2b[j];
        const float2* wb = (const float2*)(Wih2b + j * 100);
#pragma unroll 5
        for (int kh = 0; kh < 50; kh++) {
            float2 w = wb[kh];
#pragma unroll
            for (int r = 0; r < R2_; r++) {
                float2 v = *(const float2*)&xl_s[r * 100 + kh * 2];
                acc[r] = fmaf(w.x, v.x, fmaf(w.y, v.y, acc[r]));
            }
        }
#pragma unroll
        for (int r = 0; r < R2_; r++) g_s[r][j] = acc[r];
    }
    __syncthreads();

    for (int i = tid; i < R2_ * H2_; i += 608) {     // h2b + net assembly
        int r = i / H2_, k = i % H2_;
        float i_ = g_s[r][k], gg = g_s[r][2 * H2_ + k], o_ = g_s[r][3 * H2_ + k];
        float c = sigf(i_) * tanhfast(gg);
        net_s[r][150 + k] = sigf(o_) * tanhfast(c);
        net_s[r][k]       = v_s[r][k];
    }
    __syncthreads();

    float* feat = (float*)g_s;
    if (tid < 160) {                                 // waveform: 8 x 20
        int r = tid / 20, o = tid % 20;
        float a = headb[o];
        const float2* hw = (const float2*)(headW + o * 300);
#pragma unroll 10
        for (int kh = 0; kh < 150; kh++) {
            float2 w = hw[kh];
            float2 v = *(const float2*)&net_s[r][kh * 2];
            a = fmaf(w.x, v.x, fmaf(w.y, v.y, a));
        }
        a = lrelu(a);
        feat[r * 32 + o] = a;
        out[(row0 + r) * 20 + o] = a;
    }
    if (tid >= 160 && tid < 240) {                   // pef: 8 x 10
        int t2 = tid - 160, r = t2 / 10, o = t2 % 10;
        float a = p1b[o];
#pragma unroll
        for (int k = 0; k < 4; k++) a = fmaf(p1W[o * 4 + k], rrs[(row0 + r) * 4 + k], a);
        feat[r * 32 + 20 + o] = lrelu(a);
    }
    __syncthreads();

    if (tid < 16) {                                  // pef_logits: 8 x 2
        int r = tid / 2, o = tid % 2;
        float a = p2b[o];
#pragma unroll
        for (int k = 0; k < 10; k++) a = fmaf(p2W[o * 10 + k], feat[r * 32 + 20 + k], a);
        out[B_ * 20 + (row0 + r) * 2 + o] = a;
    }
    if (tid >= 32 && tid < 272) {                    // feat out: 8 x 30
        int t2 = tid - 32, r = t2 / 30, o = t2 % 30;
        out[B_ * 22 + (row0 + r) * 30 + o] = feat[r * 32 + o];
    }
    if (tid >= 288 && tid < 320) {                   // logits: 8 x 4
        int t2 = tid - 288, r = t2 / 4, o = t2 % 4;
        float a = fcb[o];
#pragma unroll
        for (int k = 0; k < 30; k++) a = fmaf(fcW[o * 30 + k], feat[r * 32 + k], a);
        out[B_ * 52 + (row0 + r) * 4 + o] = a;
    }
}

// ---------------------------------------------------------------------------
extern "C" void kernel_launch(void* const* d_in, const int* in_sizes, int n_in,
                              void* d_out, int out_size)
{
    const float* x      = (const float*)d_in[0];
    const float* rrs    = (const float*)d_in[1];
    const float* l1Wihf = (const float*)d_in[2];
    const float* l1Whhf = (const float*)d_in[3];
    const float* l1bf   = (const float*)d_in[4];
    const float* l1Wihb = (const float*)d_in[5];
    const float* l1Whhb = (const float*)d_in[6];
    const float* l1bb   = (const float*)d_in[7];
    const float* l2Wihf = (const float*)d_in[8];
    const float* l2Whhf = (const float*)d_in[9];
    const float* l2bf   = (const float*)d_in[10];
    const float* l2Wihb = (const float*)d_in[11];
    /* d_in[12] = l2_Whh_b: unused — backward L2 is a single step from h0=0 */
    const float* l2bb   = (const float*)d_in[13];
    const float* headW  = (const float*)d_in[14];
    const float* headb  = (const float*)d_in[15];
    const float* p1W    = (const float*)d_in[16];
    const float* p1b    = (const float*)d_in[17];
    const float* p2W    = (const float*)d_in[18];
    const float* p2b    = (const float*)d_in[19];
    const float* fcW    = (const float*)d_in[20];
    const float* fcb    = (const float*)d_in[21];

    cudaFuncSetAttribute(lstm2_kernel,
                         cudaFuncAttributeMaxDynamicSharedMemorySize, SMEM3_BYTES);
    cudaFuncSetAttribute(xg_gemm_kernel,
                         cudaFuncAttributeMaxDynamicSharedMemorySize, SMEMG_BYTES);

    prep_kernel<<<GP_, 128>>>(l2Whhf, l2Wihf);
    lstm1_kernel<<<dim3(B_ / R1_, 2), 256>>>(x, l1Wihf, l1Whhf, l1bf,
                                             l1Wihb, l1Whhb, l1bb);
    xg_gemm_kernel<<<MROWS / 128, 608, SMEMG_BYTES>>>(l2bf);
    lstm2_kernel<<<B_ / R2_, 608, SMEM3_BYTES>>>(l2Wihb, l2bb, rrs,
                                                 headW, headb, p1W, p1b,
                                                 p2W, p2b, fcW, fcb,
                                                 (float*)d_out);
}